// round 15
// baseline (speedup 1.0000x reference)
#include <cuda_runtime.h>
#include <cuda_fp16.h>
#include <cstdint>

#define NB 512   // buckets
#define ND 256   // feature dim
#define NMAX 100352
#define NCNT_BLK 56
#define NGRID 148

#define SE_STRIDE 520          // halves per row of exp tile (512 + 8 pad)
#define SE_BUF 66560           // one sE buffer (64 x 520 x 2B)
#define SB_OFF 133120          // per-consumer-warp B double buffers: 8 x 2 x 2560
#define SB_WARP 5120
#define SB_BUF 2560            // 32 n-rows x 80 B
#define XCOEF_OFF 174080       // 2 x 64 floats
#define XGAM_OFF  174592
#define XBET_OFF  175616
#define SMEM_TOTAL 176768
#define SH_STRIDE 260          // fp32 sH stride: 64*260*4 = 66560 = SE_BUF exactly

// ---------------- device scratch (no allocation allowed) ----------------
__device__ float g_sums[NB * ND];
__device__ float g_counts[NB];
__device__ int   g_pcnt[NCNT_BLK][NB];
__device__ int   g_off[NB + 1];
__device__ int   g_cursor[NB];
__device__ int   g_perm[NMAX];
__device__ int   g_tick1;
__device__ int   g_tick2;
__device__ __align__(16) __half g_P2t[ND * NB];  // (proto @ W_r^T)^T fp16, [d2][b]

// ---------------- helpers ----------------
__device__ __forceinline__ uint32_t smem_u32(const void* p) {
    uint32_t a;
    asm("{ .reg .u64 t; cvta.to.shared.u64 t, %1; cvt.u32.u64 %0, t; }" : "=r"(a) : "l"(p));
    return a;
}
__device__ __forceinline__ void mma_f16(float* c, const unsigned* a,
                                        unsigned b0, unsigned b1) {
    asm("mma.sync.aligned.m16n8k16.row.col.f32.f16.f16.f32 "
        "{%0,%1,%2,%3},{%4,%5,%6,%7},{%8,%9},{%0,%1,%2,%3};"
        : "+f"(c[0]), "+f"(c[1]), "+f"(c[2]), "+f"(c[3])
        : "r"(a[0]), "r"(a[1]), "r"(a[2]), "r"(a[3]), "r"(b0), "r"(b1));
}
__device__ __forceinline__ void ldmatrix_x4(unsigned* r, uint32_t addr) {
    asm volatile("ldmatrix.sync.aligned.m8n8.x4.shared.b16 {%0,%1,%2,%3}, [%4];"
        : "=r"(r[0]), "=r"(r[1]), "=r"(r[2]), "=r"(r[3]) : "r"(addr));
}
#define CP_ASYNC16(dst, src) \
    asm volatile("cp.async.cg.shared.global [%0], [%1], 16;" :: "r"(dst), "l"(src))
#define CP_COMMIT() asm volatile("cp.async.commit_group;" ::: "memory")
#define CP_WAIT1()  asm volatile("cp.async.wait_group 1;" ::: "memory")
#define BAR_SYNC(id)  asm volatile("bar.sync %0, 512;"   :: "r"(id) : "memory")
#define BAR_ARRIVE(id) asm volatile("bar.arrive %0, 512;" :: "r"(id) : "memory")
#define BAR_CONS()    asm volatile("bar.sync 5, 256;" ::: "memory")

// ---------------- dtype detect (warp-parallel) ----------------
__device__ __forceinline__ int detect_stride(const int* __restrict__ bk, int n) {
    int lane = threadIdx.x & 31;
    int acc = 0;
    int lim = min(256, n / 2);
    for (int j = lane; j < lim; j += 32) acc |= bk[2 * j + 1];
#pragma unroll
    for (int o = 16; o; o >>= 1) acc |= __shfl_xor_sync(0xffffffffu, acc, o);
    return acc ? 1 : 2;
}

// ---------------- 1: counts + scan (last-CTA ticket) ----------------
__global__ __launch_bounds__(512) void countscan_kernel(const int* __restrict__ bk, int n) {
    __shared__ int sc[NB];
    __shared__ int sstride;
    __shared__ int sticket;
    int tid = threadIdx.x;
    if (tid < 32) {
        int s = detect_stride(bk, n);
        if (tid == 0) sstride = s;
    }
    sc[tid] = 0;
    __syncthreads();
    int stride = sstride;
    for (int i = blockIdx.x * 512 + tid; i < n; i += NCNT_BLK * 512) {
        unsigned b = (unsigned)bk[(size_t)i * stride];
        if (b < NB) atomicAdd(&sc[b], 1);
    }
    __syncthreads();
    g_pcnt[blockIdx.x][tid] = sc[tid];
    __threadfence();
    if (tid == 0) sticket = atomicAdd(&g_tick1, 1);
    __syncthreads();
    if (sticket == NCNT_BLK - 1) {
        int cnt = 0;
        for (int b = 0; b < NCNT_BLK; b++) cnt += g_pcnt[b][tid];
        sc[tid] = cnt;
        __syncthreads();
#pragma unroll
        for (int o = 1; o < NB; o <<= 1) {
            int v = (tid >= o) ? sc[tid - o] : 0;
            __syncthreads();
            sc[tid] += v;
            __syncthreads();
        }
        int excl = sc[tid] - cnt;
        g_off[tid] = excl;
        g_cursor[tid] = excl;
        g_counts[tid] = (float)cnt;
        if (tid == NB - 1) g_off[NB] = sc[tid];
        if (tid == 0) g_tick1 = 0;
    }
}

// ---------------- 2: scatter permutation ----------------
__global__ void scatter_kernel(const int* __restrict__ bk, int n) {
    __shared__ int sstride;
    if (threadIdx.x < 32) {
        int s = detect_stride(bk, n);
        if (threadIdx.x == 0) sstride = s;
    }
    __syncthreads();
    int stride = sstride;
    int i = blockIdx.x * blockDim.x + threadIdx.x;
    if (i < n) {
        unsigned b = (unsigned)bk[(size_t)i * stride];
        if (b < NB) {
            int pos = atomicAdd(&g_cursor[b], 1);
            if ((unsigned)pos < (unsigned)NMAX) g_perm[pos] = i;
        }
    }
}

// ---------------- 3: bucket sums + prototype + P2 row (fused, 2-way) ----------------
__global__ __launch_bounds__(512) void bucketsum_p2_kernel(
    const float* __restrict__ V, const float* __restrict__ Wr, int n) {
    __shared__ float spart[2][ND];
    __shared__ __align__(16) float sp[ND];
    __shared__ int sticket;
    int b = blockIdx.x;
    int tid = threadIdx.x, t = tid & 255, h = tid >> 8;
    int lane = tid & 31, warp = tid >> 5;

    int s0 = g_off[b], s1 = g_off[b + 1];
    int len = s1 - s0;
    int half = (len + 1) >> 1;
    int hs = s0 + h * half;
    int he = min(s1, hs + half);
    float acc = 0.f;
    int i = hs;
    for (; i + 8 <= he; i += 8) {
        int r[8];
#pragma unroll
        for (int j = 0; j < 8; j++) r[j] = g_perm[i + j];
#pragma unroll
        for (int j = 0; j < 8; j++) acc += V[(size_t)r[j] * ND + t];
    }
    for (; i < he; i++) acc += V[(size_t)g_perm[i] * ND + t];
    spart[h][t] = acc;
    __syncthreads();

    float cnt = (float)len;
    if (h == 0) {
        float tot = spart[0][t] + spart[1][t];
        g_sums[(size_t)b * ND + t] = tot;
        sp[t] = (len > 0) ? tot / cnt : 0.f;
    }
    __syncthreads();

    const float4* sp4 = (const float4*)sp;
    if (len > 0) {
        for (int rr = 0; rr < 16; rr++) {
            int r = warp * 16 + rr;
            const float4* w4 = (const float4*)(Wr + (size_t)r * ND);
            float4 p0 = sp4[lane * 2], p1 = sp4[lane * 2 + 1];
            float4 w0 = w4[lane * 2], w1 = w4[lane * 2 + 1];
            float part = p0.x * w0.x + p0.y * w0.y + p0.z * w0.z + p0.w * w0.w +
                         p1.x * w1.x + p1.y * w1.y + p1.z * w1.z + p1.w * w1.w;
#pragma unroll
            for (int o = 16; o; o >>= 1) part += __shfl_xor_sync(0xffffffffu, part, o);
            if (lane == 0) g_P2t[(size_t)r * NB + b] = __float2half(part);
        }
    }
    __threadfence();
    if (tid == 0) sticket = atomicAdd(&g_tick2, 1);
    __syncthreads();
    if (sticket == NB - 1) {
        int any_empty = 0;
        for (int bb = tid; bb < NB; bb += 512) if (g_counts[bb] == 0.f) any_empty = 1;
        __syncthreads();
        spart[0][0] = 0.f;
        __syncthreads();
        if (any_empty) spart[0][0] = 1.f;
        __syncthreads();
        if (spart[0][0] != 0.f) {      // statistically never taken
            if (h == 0) {
                float s = 0.f;
                for (int bb = 0; bb < NB; bb++) s += g_sums[(size_t)bb * ND + t];
                sp[t] = s / (float)n;
            }
            __syncthreads();
            for (int bb = 0; bb < NB; bb++) {
                if (g_counts[bb] != 0.f) continue;
                for (int rr = 0; rr < 16; rr++) {
                    int r = warp * 16 + rr;
                    const float4* w4 = (const float4*)(Wr + (size_t)r * ND);
                    float4 p0 = sp4[lane * 2], p1 = sp4[lane * 2 + 1];
                    float4 w0 = w4[lane * 2], w1 = w4[lane * 2 + 1];
                    float part = p0.x * w0.x + p0.y * w0.y + p0.z * w0.z + p0.w * w0.w +
                                 p1.x * w1.x + p1.y * w1.y + p1.z * w1.z + p1.w * w1.w;
#pragma unroll
                    for (int o = 16; o; o >>= 1) part += __shfl_xor_sync(0xffffffffu, part, o);
                    if (lane == 0) g_P2t[(size_t)r * NB + bb] = __float2half(part);
                }
            }
        }
        if (tid == 0) g_tick2 = 0;
    }
}

// ---------------- per-row softmax core ----------------
__device__ __forceinline__ void softmax_row(const float* v, __half* sE, float* sCoef,
                                            float* outc, int r, int row, int lane) {
    float m = v[0];
#pragma unroll
    for (int k = 1; k < 16; k++) m = fmaxf(m, v[k]);
#pragma unroll
    for (int o = 16; o; o >>= 1) m = fmaxf(m, __shfl_xor_sync(0xffffffffu, m, o));
    float Z = 0.f, S = 0.f;
    unsigned h[8];
#pragma unroll
    for (int k = 0; k < 8; k++) {
        float t0 = v[2 * k] - m, t1 = v[2 * k + 1] - m;
        float e0 = __expf(t0), e1 = __expf(t1);
        Z += e0 + e1; S += e0 * t0 + e1 * t1;
        __half2 p = __floats2half2_rn(e0, e1);
        h[k] = *(unsigned*)&p;
    }
#pragma unroll
    for (int o = 16; o; o >>= 1) {
        Z += __shfl_xor_sync(0xffffffffu, Z, o);
        S += __shfl_xor_sync(0xffffffffu, S, o);
    }
    uint4* dst = (uint4*)(sE + r * SE_STRIDE + lane * 16);
    dst[0] = make_uint4(h[0], h[1], h[2], h[3]);
    dst[1] = make_uint4(h[4], h[5], h[6], h[7]);
    float logZ = __logf(Z);
    float entropy = logZ - S / Z;
    float conf = 1.f - entropy * 0.16029938f;     // 1/ln(512)
    if (lane == 0) {
        sCoef[r] = (1.f - conf) / Z;              // gate / Z
        outc[row] = conf;
    }
}

// ---------------- consumer B-chunk staging ----------------
__device__ __forceinline__ void stage_chunk(uint32_t sbW, int colbase, int kc, int buf,
                                            int lane) {
    const char* P2c = (const char*)g_P2t;
    int nr0 = lane >> 2, seg = lane & 3;
#pragma unroll
    for (int j = 0; j < 4; j++) {
        int nr = nr0 + j * 8;
        uint32_t dst = sbW + buf * SB_BUF + nr * 80 + seg * 16;
        const char* src = P2c + ((size_t)(colbase + nr) * NB + kc * 32 + seg * 8) * 2;
        CP_ASYNC16(dst, src);
    }
    CP_COMMIT();
}

// ---------------- 4: persistent warp-specialized main ----------------
// grid 148, 512 threads, 1 CTA/SM. Warps 0-7 = consumers (GEMM),
// warps 8-15 = producers (softmax Phase A + LayerNorm Phase C).
// sE double-buffered; sH(t) overlays sE[buf(t)] after B(t).
// R_i (ids 1,2): producer bar.arrive, consumer bar.sync.
// S_i (ids 3,4): consumer bar.arrive, producer bar.sync.
__global__ __launch_bounds__(512, 1) void main_kernel(
    const float* __restrict__ logits, const float* __restrict__ hfused,
    const float* __restrict__ gamma, const float* __restrict__ beta,
    float* __restrict__ outh, float* __restrict__ outc, int n) {
    extern __shared__ __align__(16) char smem[];
    float* sGam = (float*)(smem + XGAM_OFF);
    float* sBet = (float*)(smem + XBET_OFF);
    uint32_t sbase = smem_u32(smem);

    int tid = threadIdx.x, lane = tid & 31, warp = tid >> 5;
    int ntiles = (n + 63) / 64;
    int nt = (ntiles > (int)blockIdx.x) ? (ntiles - blockIdx.x + NGRID - 1) / NGRID : 0;

    if (tid < 256) { sGam[tid] = gamma[tid]; sBet[tid] = beta[tid]; }
    __syncthreads();
    if (nt == 0) return;

    if (warp >= 8) {
        // ================= PRODUCER =================
        int pw = warp - 8;
        // Phase A for tile index i into buf (i&1)
        auto prodA = [&](int i, int buf) {
            __half* sE = (__half*)(smem + buf * SE_BUF);
            float* sCoef = (float*)(smem + XCOEF_OFF + buf * 256);
            int row0 = (blockIdx.x + i * NGRID) * 64;
#pragma unroll 1
            for (int rr = 0; rr < 8; rr++) {
                int r = pw * 8 + rr;
                int row = row0 + r;
                if (row < n) {
                    const float* lrow = logits + (size_t)row * NB + lane * 16;
                    float v[16];
#pragma unroll
                    for (int qq = 0; qq < 4; qq++) {
                        float4 f = *(const float4*)(lrow + 4 * qq);
                        v[4 * qq] = f.x; v[4 * qq + 1] = f.y;
                        v[4 * qq + 2] = f.z; v[4 * qq + 3] = f.w;
                    }
                    softmax_row(v, sE, sCoef, outc, r, row, lane);
                } else {
                    uint4* dst = (uint4*)(sE + r * SE_STRIDE + lane * 16);
                    dst[0] = make_uint4(0, 0, 0, 0);
                    dst[1] = make_uint4(0, 0, 0, 0);
                    if (lane == 0) sCoef[r] = 0.f;
                }
            }
        };
        // Phase C for tile i from sH overlaying buf (i&1)
        auto prodC = [&](int i, int buf) {
            const float* sH = (const float*)(smem + buf * SE_BUF);
            const float* sCoef = (const float*)(smem + XCOEF_OFF + buf * 256);
            int row0 = (blockIdx.x + i * NGRID) * 64;
#pragma unroll 1
            for (int rr = 0; rr < 8; rr++) {
                int r = pw * 8 + rr;
                int row = row0 + r;
                if (row < n) {
                    float coef = sCoef[r];
                    const float* hrow = hfused + (size_t)row * ND;
                    float x[8];
                    float s = 0.f, s2 = 0.f;
#pragma unroll
                    for (int k = 0; k < 8; k++) {
                        int c = lane + 32 * k;
                        x[k] = hrow[c] + coef * sH[r * SH_STRIDE + c];
                        s += x[k]; s2 += x[k] * x[k];
                    }
#pragma unroll
                    for (int o = 16; o; o >>= 1) {
                        s += __shfl_xor_sync(0xffffffffu, s, o);
                        s2 += __shfl_xor_sync(0xffffffffu, s2, o);
                    }
                    float mean = s * (1.f / ND);
                    float var = s2 * (1.f / ND) - mean * mean;
                    float rstd = rsqrtf(var + 1e-5f);
                    float* orow = outh + (size_t)row * ND;
#pragma unroll
                    for (int k = 0; k < 8; k++) {
                        int c = lane + 32 * k;
                        orow[c] = (x[k] - mean) * rstd * sGam[c] + sBet[c];
                    }
                }
            }
        };

        prodA(0, 0);
        BAR_ARRIVE(1);                       // R_0
        if (nt > 1) { prodA(1, 1); BAR_ARRIVE(2); }   // R_1
        for (int i = 0; i < nt; i++) {
            int buf = i & 1;
            BAR_SYNC(3 + buf);               // S_i : sH_i ready
            prodC(i, buf);
            if (i + 2 < nt) { prodA(i + 2, buf); BAR_ARRIVE(1 + buf); }  // R_{i+2}
        }
    } else {
        // ================= CONSUMER =================
        int colbase = warp * 32;
        uint32_t sbW = sbase + SB_OFF + warp * SB_WARP;
        int t4 = lane >> 3, r8 = lane & 7;
        uint32_t aFrag = (((uint32_t)((t4 & 1) * 8 + r8)) * SE_STRIDE +
                          (uint32_t)(t4 >> 1) * 8) * 2;
        uint32_t bTileOff = ((uint32_t)((t4 >> 1) * 8 + r8)) * 80u + (uint32_t)(t4 & 1) * 16u;
        int g = lane >> 2, tg = lane & 3;

        for (int i = 0; i < nt; i++) {
            int buf = i & 1;
            // prefetch B chunks 0,1 (cp.async; overlaps the R_i wait)
            stage_chunk(sbW, colbase, 0, 0, lane);
            stage_chunk(sbW, colbase, 1, 1, lane);
            BAR_SYNC(1 + buf);               // R_i : sE[buf] ready

            uint32_t aBase = sbase + buf * SE_BUF + aFrag;
            float acc[4][4][4];
#pragma unroll
            for (int mt = 0; mt < 4; mt++)
#pragma unroll
                for (int ntt = 0; ntt < 4; ntt++)
#pragma unroll
                    for (int q = 0; q < 4; q++) acc[mt][ntt][q] = 0.f;

            for (int kc = 0; kc < 16; kc++) {
                int bbuf = kc & 1;
                CP_WAIT1();
                uint32_t bBuf = sbW + bbuf * SB_BUF + bTileOff;
#pragma unroll
                for (int ks = 0; ks < 2; ks++) {
                    unsigned a[4][4];
#pragma unroll
                    for (int mt = 0; mt < 4; mt++)
                        ldmatrix_x4(a[mt], aBase +
                            (uint32_t)(mt * 16 * SE_STRIDE + kc * 32 + ks * 16) * 2);
                    unsigned bb[8];
                    ldmatrix_x4(bb,     bBuf + ks * 32);
                    ldmatrix_x4(bb + 4, bBuf + 16 * 80 + ks * 32);
#pragma unroll
                    for (int ntt = 0; ntt < 4; ntt++)
#pragma unroll
                        for (int mt = 0; mt < 4; mt++)
                            mma_f16(acc[mt][ntt], a[mt], bb[2 * ntt], bb[2 * ntt + 1]);
                }
                if (kc + 2 < 16) stage_chunk(sbW, colbase, kc + 2, bbuf, lane);
                else CP_COMMIT();
            }
            BAR_CONS();   // all consumer warps done reading sE[buf] (A frags)
            // write sH overlaying sE[buf]
            float* sH = (float*)(smem + buf * SE_BUF);
#pragma unroll
            for (int mt = 0; mt < 4; mt++) {
                int rb = mt * 16;
#pragma unroll
                for (int ntt = 0; ntt < 4; ntt++) {
                    int cb = colbase + ntt * 8 + 2 * tg;
                    sH[(rb + g) * SH_STRIDE + cb]         = acc[mt][ntt][0];
                    sH[(rb + g) * SH_STRIDE + cb + 1]     = acc[mt][ntt][1];
                    sH[(rb + g + 8) * SH_STRIDE + cb]     = acc[mt][ntt][2];
                    sH[(rb + g + 8) * SH_STRIDE + cb + 1] = acc[mt][ntt][3];
                }
            }
            BAR_ARRIVE(3 + buf);             // S_i : sH_i ready
        }
    }
}

// ---------------- launch ----------------
extern "C" void kernel_launch(void* const* d_in, const int* in_sizes, int n_in,
                              void* d_out, int out_size) {
    const float* h_fused = (const float*)d_in[0];
    const float* V       = (const float*)d_in[1];
    const float* logits  = (const float*)d_in[2];
    const int*   bk32    = (const int*)d_in[3];
    const float* Wr      = (const float*)d_in[4];
    const float* gamma   = (const float*)d_in[5];
    const float* beta    = (const float*)d_in[6];
    int n = in_sizes[0] / ND;

    float* outh = (float*)d_out;
    float* outc = outh + (size_t)n * ND;

    cudaFuncSetAttribute(main_kernel, cudaFuncAttributeMaxDynamicSharedMemorySize,
                         SMEM_TOTAL);

    countscan_kernel<<<NCNT_BLK, 512>>>(bk32, n);                    // 1
    scatter_kernel<<<(n + 511) / 512, 512>>>(bk32, n);               // 2
    bucketsum_p2_kernel<<<NB, 512>>>(V, Wr, n);                      // 3
    main_kernel<<<NGRID, 512, SMEM_TOTAL>>>(logits, h_fused, gamma, beta,
                                            outh, outc, n);          // 4 (ncu window)
}

// round 16
// speedup vs baseline: 1.2078x; 1.2078x over previous
#include <cuda_runtime.h>
#include <cuda_fp16.h>
#include <cstdint>

#define NB 512   // buckets
#define ND 256   // feature dim
#define NMAX 100352
#define NCNT_BLK 56

#define SE_STRIDE 520          // halves per row of exp tile (512 + 8 pad)
#define SE_OFF 0               // 64 x 520 halves = 66560 B
#define SB_OFF 66560           // per-warp B double buffers: 8 x 2 x 2560 B
#define SB_WARP 5120           // 2 bufs x 2560
#define SB_BUF 2560            // 32 n-rows x 80 B
#define XCOEF_OFF 107520       // 64 floats
#define SMEM_TOTAL (107520 + 256 + 32)
#define SH_STRIDE 264          // fp32 epilogue tile stride (overlaps sE/sB region)

// ---------------- device scratch (no allocation allowed) ----------------
__device__ float g_sums[NB * ND];
__device__ float g_counts[NB];
__device__ int   g_pcnt[NCNT_BLK][NB];
__device__ int   g_off[NB + 1];
__device__ int   g_cursor[NB];
__device__ int   g_perm[NMAX];
__device__ int   g_tick1;   // countscan ticket (reset each run)
__device__ int   g_tick2;   // bucketsum_p2 ticket (reset each run)
__device__ __align__(16) __half g_P2t[ND * NB];  // (proto @ W_r^T)^T fp16, [d2][b]

// ---------------- helpers ----------------
__device__ __forceinline__ uint32_t smem_u32(const void* p) {
    uint32_t a;
    asm("{ .reg .u64 t; cvta.to.shared.u64 t, %1; cvt.u32.u64 %0, t; }" : "=r"(a) : "l"(p));
    return a;
}
__device__ __forceinline__ void mma_f16(float* c, const unsigned* a,
                                        unsigned b0, unsigned b1) {
    asm("mma.sync.aligned.m16n8k16.row.col.f32.f16.f16.f32 "
        "{%0,%1,%2,%3},{%4,%5,%6,%7},{%8,%9},{%0,%1,%2,%3};"
        : "+f"(c[0]), "+f"(c[1]), "+f"(c[2]), "+f"(c[3])
        : "r"(a[0]), "r"(a[1]), "r"(a[2]), "r"(a[3]), "r"(b0), "r"(b1));
}
__device__ __forceinline__ void ldmatrix_x4(unsigned* r, uint32_t addr) {
    asm volatile("ldmatrix.sync.aligned.m8n8.x4.shared.b16 {%0,%1,%2,%3}, [%4];"
        : "=r"(r[0]), "=r"(r[1]), "=r"(r[2]), "=r"(r[3]) : "r"(addr));
}
#define CP_ASYNC16(dst, src) \
    asm volatile("cp.async.cg.shared.global [%0], [%1], 16;" :: "r"(dst), "l"(src))
#define CP_COMMIT() asm volatile("cp.async.commit_group;" ::: "memory")
#define CP_WAIT1()  asm volatile("cp.async.wait_group 1;" ::: "memory")
#define PREFETCH_L2(p) asm volatile("prefetch.global.L2 [%0];" :: "l"(p))

// ---------------- dtype detect (warp-parallel) ----------------
__device__ __forceinline__ int detect_stride(const int* __restrict__ bk, int n) {
    int lane = threadIdx.x & 31;
    int acc = 0;
    int lim = min(256, n / 2);
    for (int j = lane; j < lim; j += 32) acc |= bk[2 * j + 1];
#pragma unroll
    for (int o = 16; o; o >>= 1) acc |= __shfl_xor_sync(0xffffffffu, acc, o);
    return acc ? 1 : 2;
}

// ---------------- 1: counts + scan (last-CTA ticket) ----------------
__global__ __launch_bounds__(512) void countscan_kernel(const int* __restrict__ bk, int n) {
    __shared__ int sc[NB];
    __shared__ int sstride;
    __shared__ int sticket;
    int tid = threadIdx.x;
    if (tid < 32) {
        int s = detect_stride(bk, n);
        if (tid == 0) sstride = s;
    }
    sc[tid] = 0;
    __syncthreads();
    int stride = sstride;
    for (int i = blockIdx.x * 512 + tid; i < n; i += NCNT_BLK * 512) {
        unsigned b = (unsigned)bk[(size_t)i * stride];
        if (b < NB) atomicAdd(&sc[b], 1);
    }
    __syncthreads();
    g_pcnt[blockIdx.x][tid] = sc[tid];
    __threadfence();
    if (tid == 0) sticket = atomicAdd(&g_tick1, 1);
    __syncthreads();
    if (sticket == NCNT_BLK - 1) {   // last CTA: reduce + scan
        int cnt = 0;
        for (int b = 0; b < NCNT_BLK; b++) cnt += g_pcnt[b][tid];
        sc[tid] = cnt;
        __syncthreads();
#pragma unroll
        for (int o = 1; o < NB; o <<= 1) {
            int v = (tid >= o) ? sc[tid - o] : 0;
            __syncthreads();
            sc[tid] += v;
            __syncthreads();
        }
        int excl = sc[tid] - cnt;
        g_off[tid] = excl;
        g_cursor[tid] = excl;
        g_counts[tid] = (float)cnt;
        if (tid == NB - 1) g_off[NB] = sc[tid];
        if (tid == 0) g_tick1 = 0;   // reset for next graph replay
    }
}

// ---------------- 2: scatter permutation ----------------
__global__ void scatter_kernel(const int* __restrict__ bk, int n) {
    __shared__ int sstride;
    if (threadIdx.x < 32) {
        int s = detect_stride(bk, n);
        if (threadIdx.x == 0) sstride = s;
    }
    __syncthreads();
    int stride = sstride;
    int i = blockIdx.x * blockDim.x + threadIdx.x;
    if (i < n) {
        unsigned b = (unsigned)bk[(size_t)i * stride];
        if (b < NB) {
            int pos = atomicAdd(&g_cursor[b], 1);
            if ((unsigned)pos < (unsigned)NMAX) g_perm[pos] = i;
        }
    }
}

// ---------------- 3: bucket sums + prototype + P2 row (fused, 2-way) ----------------
// CTA b, 512 threads: t = col (0..255), h = row-half (0/1).
__global__ __launch_bounds__(512) void bucketsum_p2_kernel(
    const float* __restrict__ V, const float* __restrict__ Wr, int n) {
    __shared__ float spart[2][ND];
    __shared__ __align__(16) float sp[ND];
    __shared__ int sticket;
    int b = blockIdx.x;
    int tid = threadIdx.x, t = tid & 255, h = tid >> 8;
    int lane = tid & 31, warp = tid >> 5;

    int s0 = g_off[b], s1 = g_off[b + 1];
    int len = s1 - s0;
    int half = (len + 1) >> 1;
    int hs = s0 + h * half;
    int he = min(s1, hs + half);
    float acc = 0.f;
    int i = hs;
    for (; i + 8 <= he; i += 8) {
        int r[8];
#pragma unroll
        for (int j = 0; j < 8; j++) r[j] = __ldcs(&g_perm[i + j]);
#pragma unroll
        for (int j = 0; j < 8; j++) acc += __ldcs(&V[(size_t)r[j] * ND + t]);
    }
    for (; i < he; i++) acc += __ldcs(&V[(size_t)g_perm[i] * ND + t]);
    spart[h][t] = acc;
    __syncthreads();

    float cnt = (float)len;
    if (h == 0) {
        float tot = spart[0][t] + spart[1][t];
        g_sums[(size_t)b * ND + t] = tot;
        sp[t] = (len > 0) ? tot / cnt : 0.f;
    }
    __syncthreads();

    // P2 row: warp w computes rows [w*16, w*16+16); lane covers 8 contiguous d.
    const float4* sp4 = (const float4*)sp;
    if (len > 0) {
        for (int rr = 0; rr < 16; rr++) {
            int r = warp * 16 + rr;
            const float4* w4 = (const float4*)(Wr + (size_t)r * ND);
            float4 p0 = sp4[lane * 2], p1 = sp4[lane * 2 + 1];
            float4 w0 = w4[lane * 2], w1 = w4[lane * 2 + 1];
            float part = p0.x * w0.x + p0.y * w0.y + p0.z * w0.z + p0.w * w0.w +
                         p1.x * w1.x + p1.y * w1.y + p1.z * w1.z + p1.w * w1.w;
#pragma unroll
            for (int o = 16; o; o >>= 1) part += __shfl_xor_sync(0xffffffffu, part, o);
            if (lane == 0) g_P2t[(size_t)r * NB + b] = __float2half(part);
        }
    }
    __threadfence();
    if (tid == 0) sticket = atomicAdd(&g_tick2, 1);
    __syncthreads();
    if (sticket == NB - 1) {
        int any_empty = 0;
        for (int bb = tid; bb < NB; bb += 512) if (g_counts[bb] == 0.f) any_empty = 1;
        __syncthreads();
        spart[0][0] = 0.f;
        __syncthreads();
        if (any_empty) spart[0][0] = 1.f;
        __syncthreads();
        if (spart[0][0] != 0.f) {      // statistically never taken
            if (h == 0) {
                float s = 0.f;
                for (int bb = 0; bb < NB; bb++) s += g_sums[(size_t)bb * ND + t];
                sp[t] = s / (float)n;
            }
            __syncthreads();
            for (int bb = 0; bb < NB; bb++) {
                if (g_counts[bb] != 0.f) continue;
                for (int rr = 0; rr < 16; rr++) {
                    int r = warp * 16 + rr;
                    const float4* w4 = (const float4*)(Wr + (size_t)r * ND);
                    float4 p0 = sp4[lane * 2], p1 = sp4[lane * 2 + 1];
                    float4 w0 = w4[lane * 2], w1 = w4[lane * 2 + 1];
                    float part = p0.x * w0.x + p0.y * w0.y + p0.z * w0.z + p0.w * w0.w +
                                 p1.x * w1.x + p1.y * w1.y + p1.z * w1.z + p1.w * w1.w;
#pragma unroll
                    for (int o = 16; o; o >>= 1) part += __shfl_xor_sync(0xffffffffu, part, o);
                    if (lane == 0) g_P2t[(size_t)r * NB + bb] = __float2half(part);
                }
            }
        }
        if (tid == 0) g_tick2 = 0;
    }
}

// ---------------- per-row softmax core (computes + stores exp row r) ----------------
__device__ __forceinline__ void softmax_row(const float* v, __half* sE, float* sCoef,
                                            float* outc, int r, int row, int lane) {
    float m = v[0];
#pragma unroll
    for (int k = 1; k < 16; k++) m = fmaxf(m, v[k]);
#pragma unroll
    for (int o = 16; o; o >>= 1) m = fmaxf(m, __shfl_xor_sync(0xffffffffu, m, o));
    float Z = 0.f, S = 0.f;
    unsigned h[8];
#pragma unroll
    for (int k = 0; k < 8; k++) {
        float t0 = v[2 * k] - m, t1 = v[2 * k + 1] - m;
        float e0 = __expf(t0), e1 = __expf(t1);
        Z += e0 + e1; S += e0 * t0 + e1 * t1;
        __half2 p = __floats2half2_rn(e0, e1);
        h[k] = *(unsigned*)&p;
    }
#pragma unroll
    for (int o = 16; o; o >>= 1) {
        Z += __shfl_xor_sync(0xffffffffu, Z, o);
        S += __shfl_xor_sync(0xffffffffu, S, o);
    }
    uint4* dst = (uint4*)(sE + r * SE_STRIDE + lane * 16);
    dst[0] = make_uint4(h[0], h[1], h[2], h[3]);
    dst[1] = make_uint4(h[4], h[5], h[6], h[7]);
    float logZ = __logf(Z);
    float entropy = logZ - S / Z;
    float conf = 1.f - entropy * 0.16029938f;     // 1/ln(512)
    if (lane == 0) {
        sCoef[r] = (1.f - conf) / Z;              // gate / Z
        outc[row] = conf;
    }
}

// ---------------- 4: fused main (fp16 mma + warp-private cp.async pipeline) ----------------
// CTA: 64 rows x 256 cols. Phase A: softmax -> fp16 exp tile (B prefetch in
// flight; hfused tile prefetched to L2). Phase B: 16 K-chunks of 32,
// warp-private double-buffered cp.async, no CTA barriers in the loop.
// Phase C: gate+add h_fused, LayerNorm, streaming stores.
__global__ __launch_bounds__(256, 2) void main_kernel(
    const float* __restrict__ logits, const float* __restrict__ hfused,
    const float* __restrict__ gamma, const float* __restrict__ beta,
    float* __restrict__ outh, float* __restrict__ outc, int n) {
    extern __shared__ __align__(16) char smem[];
    __half* sE = (__half*)(smem + SE_OFF);
    float* sCoef = (float*)(smem + XCOEF_OFF);
    uint32_t sbase = smem_u32(smem);

    int row0 = blockIdx.x * 64;
    int tid = threadIdx.x, lane = tid & 31, warp = tid >> 5;
    int g = lane >> 2, tg = lane & 3;
    int colbase = warp * 32;

    const char* P2c = (const char*)g_P2t;
    uint32_t sbW = sbase + SB_OFF + warp * SB_WARP;
    int stg_nr = lane >> 2, stg_seg = lane & 3;
#define STAGE_CHUNK(kc, buf)                                                     \
    do {                                                                         \
        _Pragma("unroll")                                                        \
        for (int j = 0; j < 4; j++) {                                            \
            int nr = stg_nr + j * 8;                                             \
            uint32_t dst = sbW + (buf) * SB_BUF + nr * 80 + stg_seg * 16;        \
            const char* src = P2c +                                              \
                ((size_t)(colbase + nr) * NB + (kc) * 32 + stg_seg * 8) * 2;     \
            CP_ASYNC16(dst, src);                                                \
        }                                                                        \
        CP_COMMIT();                                                             \
    } while (0)

    STAGE_CHUNK(0, 0);
    STAGE_CHUNK(1, 1);

    // L2 prefetch of this CTA's hfused tile (64 rows x 1KB = 512 lines; 2/thread).
    {
        const char* hbase = (const char*)(hfused + (size_t)row0 * ND);
        long long maxoff = ((long long)n - row0) * ND * 4;
#pragma unroll
        for (int j = 0; j < 2; j++) {
            long long off = (long long)(tid + j * 256) * 128;
            if (off < maxoff) PREFETCH_L2(hbase + off);
        }
    }

    // ---- Phase A: per-row softmax stats (each warp: 8 rows; lane owns 16 cols)
#pragma unroll
    for (int rr = 0; rr < 8; rr++) {
        int r = warp * 8 + rr;
        int row = row0 + r;
        if (row < n) {
            const float* lrow = logits + (size_t)row * NB + lane * 16;
            float v[16];
#pragma unroll
            for (int qq = 0; qq < 4; qq++) {
                float4 f = __ldcs((const float4*)(lrow + 4 * qq));   // read-once stream
                v[4 * qq] = f.x; v[4 * qq + 1] = f.y;
                v[4 * qq + 2] = f.z; v[4 * qq + 3] = f.w;
            }
            softmax_row(v, sE, sCoef, outc, r, row, lane);
        } else {
            uint4* dst = (uint4*)(sE + r * SE_STRIDE + lane * 16);
            dst[0] = make_uint4(0, 0, 0, 0);
            dst[1] = make_uint4(0, 0, 0, 0);
            if (lane == 0) sCoef[r] = 0.f;
        }
    }
    __syncthreads();   // sE complete (A fragments cross warps)

    // ---- Phase B: acc = ehat @ P2, 16 K-chunks of 32, warp-private pipeline
    float acc[4][4][4];
#pragma unroll
    for (int mt = 0; mt < 4; mt++)
#pragma unroll
        for (int nt = 0; nt < 4; nt++)
#pragma unroll
            for (int q = 0; q < 4; q++) acc[mt][nt][q] = 0.f;

    int t4 = lane >> 3, r8 = lane & 7;
    uint32_t aBase = sbase + SE_OFF +
        (((uint32_t)((t4 & 1) * 8 + r8)) * SE_STRIDE + (uint32_t)(t4 >> 1) * 8) * 2;
    uint32_t bTileOff = ((uint32_t)((t4 >> 1) * 8 + r8)) * 80u + (uint32_t)(t4 & 1) * 16u;

    for (int kc = 0; kc < 16; kc++) {
        int buf = kc & 1;
        CP_WAIT1();
        uint32_t bBuf = sbW + buf * SB_BUF + bTileOff;
#pragma unroll
        for (int ks = 0; ks < 2; ks++) {
            unsigned a[4][4];
#pragma unroll
            for (int mt = 0; mt < 4; mt++)
                ldmatrix_x4(a[mt], aBase + (uint32_t)(mt * 16 * SE_STRIDE + kc * 32 + ks * 16) * 2);
            unsigned bb[8];
            ldmatrix_x4(bb,     bBuf + ks * 32);              // nt 0,1
            ldmatrix_x4(bb + 4, bBuf + 16 * 80 + ks * 32);    // nt 2,3
#pragma unroll
            for (int nt = 0; nt < 4; nt++)
#pragma unroll
                for (int mt = 0; mt < 4; mt++)
                    mma_f16(acc[mt][nt], a[mt], bb[2 * nt], bb[2 * nt + 1]);
        }
        if (kc + 2 < 16) STAGE_CHUNK(kc + 2, buf);
        else CP_COMMIT();
    }
    __syncthreads();

    // ---- Phase C: fragments -> smem fp32 [64][SH_STRIDE]
    float* sH = (float*)smem;
#pragma unroll
    for (int mt = 0; mt < 4; mt++) {
        int rb = mt * 16;
#pragma unroll
        for (int nt = 0; nt < 4; nt++) {
            int cb = colbase + nt * 8 + 2 * tg;
            sH[(rb + g) * SH_STRIDE + cb]         = acc[mt][nt][0];
            sH[(rb + g) * SH_STRIDE + cb + 1]     = acc[mt][nt][1];
            sH[(rb + g + 8) * SH_STRIDE + cb]     = acc[mt][nt][2];
            sH[(rb + g + 8) * SH_STRIDE + cb + 1] = acc[mt][nt][3];
        }
    }
    __syncthreads();

    // ---- LayerNorm per row (each warp: 8 rows); streaming stores
    float gam[8], bet[8];
#pragma unroll
    for (int k = 0; k < 8; k++) { gam[k] = gamma[lane + 32 * k]; bet[k] = beta[lane + 32 * k]; }
#pragma unroll
    for (int rr = 0; rr < 8; rr++) {
        int r = warp * 8 + rr;
        int row = row0 + r;
        if (row < n) {
            float coef = sCoef[r];
            const float* hrow = hfused + (size_t)row * ND;
            float x[8];
            float s = 0.f, s2 = 0.f;
#pragma unroll
            for (int k = 0; k < 8; k++) {
                int c = lane + 32 * k;
                x[k] = hrow[c] + coef * sH[r * SH_STRIDE + c];
                s += x[k]; s2 += x[k] * x[k];
            }
#pragma unroll
            for (int o = 16; o; o >>= 1) {
                s += __shfl_xor_sync(0xffffffffu, s, o);
                s2 += __shfl_xor_sync(0xffffffffu, s2, o);
            }
            float mean = s * (1.f / ND);
            float var = s2 * (1.f / ND) - mean * mean;
            float rstd = rsqrtf(var + 1e-5f);
            float* orow = outh + (size_t)row * ND;
#pragma unroll
            for (int k = 0; k < 8; k++) {
                int c = lane + 32 * k;
                __stcs(&orow[c], (x[k] - mean) * rstd * gam[k] + bet[k]);
            }
        }
    }
}

// ---------------- launch ----------------
extern "C" void kernel_launch(void* const* d_in, const int* in_sizes, int n_in,
                              void* d_out, int out_size) {
    const float* h_fused = (const float*)d_in[0];
    const float* V       = (const float*)d_in[1];
    const float* logits  = (const float*)d_in[2];
    const int*   bk32    = (const int*)d_in[3];
    const float* Wr      = (const float*)d_in[4];
    const float* gamma   = (const float*)d_in[5];
    const float* beta    = (const float*)d_in[6];
    int n = in_sizes[0] / ND;

    float* outh = (float*)d_out;
    float* outc = outh + (size_t)n * ND;

    cudaFuncSetAttribute(main_kernel, cudaFuncAttributeMaxDynamicSharedMemorySize,
                         SMEM_TOTAL);

    countscan_kernel<<<NCNT_BLK, 512>>>(bk32, n);                    // 1
    scatter_kernel<<<(n + 511) / 512, 512>>>(bk32, n);               // 2
    bucketsum_p2_kernel<<<NB, 512>>>(V, Wr, n);                      // 3
    main_kernel<<<(n + 63) / 64, 256, SMEM_TOTAL>>>(logits, h_fused, gamma, beta,
                                                    outh, outc, n);  // 4 (ncu window)
}